// round 9
// baseline (speedup 1.0000x reference)
#include <cuda_runtime.h>
#include <stdint.h>

#define D 512               // embedding dim (fixed by problem)
#define EPS 1e-6f
#define NODE_CAP 50000      // capacity of the static int8 copy

#define GRP 2               // edges per pipeline stage
#define STG 3               // pipeline depth
#define ITERS 4             // groups per warp
#define EPW (GRP * ITERS)   // edges per warp = 8

// Runtime index-dtype flag: 1 if edge_index is int64, 0 if int32.
__device__ int g_idx_is64;

// int8 copy of z: one row = 512 bytes. 25.6 MB (mostly L2-resident).
__device__ __align__(16) unsigned char g_q8[(size_t)NODE_CAP * 512];
// combined per-node constants: c.x = (absmax/127)*inv_norm, c.y = sum*inv_norm
__device__ float2 g_c[NODE_CAP];

// Standalone detect (only used on the fp32 fallback path)
__global__ void detect_idx_dtype_kernel(const int* __restrict__ raw)
{
    int lane = threadIdx.x & 31;
    int lo = raw[2 * lane];
    int hi = raw[2 * lane + 1];
    unsigned bad = __ballot_sync(0xFFFFFFFFu, hi != 0 || lo < 0);
    if (lane == 0) g_idx_is64 = (bad == 0) ? 1 : 0;
}

__device__ __forceinline__ unsigned pack4_q(float4 v, float k)
{
    int q0 = __float2int_rn(v.x * k);
    int q1 = __float2int_rn(v.y * k);
    int q2 = __float2int_rn(v.z * k);
    int q3 = __float2int_rn(v.w * k);
    return (q0 & 0xFF) | ((q1 & 0xFF) << 8) | ((q2 & 0xFF) << 16)
         | ((q3 & 0xFF) << 24);
}

// Pass 1: one warp per node. Stream z row with __ldcs (evict-first),
// compute exact fp32 norm/sum and absmax, quantize to int8.
// Warp 0 additionally performs index-dtype detection.
__global__ void __launch_bounds__(256)
prep_q8_kernel(const float4* __restrict__ z4,
               const int* __restrict__ raw_edges,
               int n_nodes)
{
    int warp = (blockIdx.x * blockDim.x + threadIdx.x) >> 5;
    int lane = threadIdx.x & 31;

    if (warp == 0) {
        // int64 little-endian indices in [0, n_nodes) => hi word always 0.
        int lo = raw_edges[2 * lane];
        int hi = raw_edges[2 * lane + 1];
        unsigned bad = __ballot_sync(0xFFFFFFFFu, hi != 0 || lo < 0);
        if (lane == 0) g_idx_is64 = (bad == 0) ? 1 : 0;
    }
    if (warp >= n_nodes) return;

    const float4* __restrict__ R = z4 + (size_t)warp * (D / 4);
    float4 v[4];
#pragma unroll
    for (int j = 0; j < 4; j++) v[j] = __ldcs(&R[lane + 32 * j]);

    float na2 = 0.f, sa = 0.f, mx = 0.f;
#pragma unroll
    for (int j = 0; j < 4; j++) {
        float4 a = v[j];
        na2 = fmaf(a.x, a.x, na2); na2 = fmaf(a.y, a.y, na2);
        na2 = fmaf(a.z, a.z, na2); na2 = fmaf(a.w, a.w, na2);
        sa += a.x + a.y + a.z + a.w;
        mx = fmaxf(mx, fmaxf(fmaxf(fabsf(a.x), fabsf(a.y)),
                             fmaxf(fabsf(a.z), fabsf(a.w))));
    }

#pragma unroll
    for (int off = 16; off > 0; off >>= 1) {
        na2 += __shfl_xor_sync(0xFFFFFFFFu, na2, off);
        sa  += __shfl_xor_sync(0xFFFFFFFFu, sa,  off);
        mx  = fmaxf(mx, __shfl_xor_sync(0xFFFFFFFFu, mx, off));
    }

    mx = fmaxf(mx, 1e-20f);
    float k = 127.0f / mx;

    uint4 q;
    q.x = pack4_q(v[0], k);
    q.y = pack4_q(v[1], k);
    q.z = pack4_q(v[2], k);
    q.w = pack4_q(v[3], k);
    reinterpret_cast<uint4*>(g_q8)[(size_t)warp * 32 + lane] = q;

    if (lane == 0) {
        float inv = rsqrtf(na2);
        float2 c;
        c.x = mx * (1.0f / 127.0f) * inv;   // dequant * inv_norm (for dot)
        c.y = sa * inv;                     // sum * inv_norm     (for eps term)
        g_c[warp] = c;
    }
}

// Pass 2: software-pipelined cp.async edge decoder.
// Each warp handles 8 edges as 4 groups of 2, staged through a 3-deep
// shared-memory ring (2 KB per stage). Loads for group i+2 overlap compute
// of group i — LDGSTS traffic stays continuously in flight instead of the
// issue-wait-compute bursts of the previous version.
__global__ void __launch_bounds__(128)
edge_decoder_pipe_kernel(const void* __restrict__ edge_index,
                         float* __restrict__ out,
                         int n_edges)
{
    // 4 warps/block * 3 stages * (2 edges * 2 rows * 512B = 2 KB) = 24 KB
    __shared__ __align__(16) unsigned char sbuf[4][STG][GRP * 2 * 512];

    int wslot = threadIdx.x >> 5;
    int lane  = threadIdx.x & 31;
    int warp  = blockIdx.x * 4 + wslot;
    int ebase = warp * EPW;
    if (ebase >= n_edges) return;

    // Prefetch all 16 node indices (int32; node ids < 50K). Broadcast loads,
    // fully independent -> one latency for the whole warp's index needs.
    int ia[EPW], ib[EPW];
    if (g_idx_is64) {
        const long long* ei = (const long long*)edge_index;
#pragma unroll
        for (int j = 0; j < EPW; j++) {
            int e = min(ebase + j, n_edges - 1);
            ia[j] = (int)ei[e];
            ib[j] = (int)ei[e + n_edges];
        }
    } else {
        const int* ei = (const int*)edge_index;
#pragma unroll
        for (int j = 0; j < EPW; j++) {
            int e = min(ebase + j, n_edges - 1);
            ia[j] = ei[e];
            ib[j] = ei[e + n_edges];
        }
    }

    unsigned sbase;
    {
        void* p = &sbuf[wslot][0][0];
        asm("{ .reg .u64 t; cvta.to.shared.u64 t, %1; cvt.u32.u64 %0, t; }"
            : "=r"(sbase) : "l"(p));
    }

    // Issue one group's 4 rows (2 edges x 2 endpoints), 1 x 16B per lane each.
    auto issue_group = [&](int g, int s) {
        unsigned sb = sbase + s * (GRP * 2 * 512) + lane * 16;
#pragma unroll
        for (int j = 0; j < GRP; j++) {
            const unsigned char* srcA =
                g_q8 + (size_t)ia[g * GRP + j] * 512 + lane * 16;
            const unsigned char* srcB =
                g_q8 + (size_t)ib[g * GRP + j] * 512 + lane * 16;
            asm volatile("cp.async.cg.shared.global [%0], [%1], 16;"
                         :: "r"(sb + j * 512), "l"(srcA) : "memory");
            asm volatile("cp.async.cg.shared.global [%0], [%1], 16;"
                         :: "r"(sb + (GRP + j) * 512), "l"(srcB) : "memory");
        }
    };

    // Prologue: fill stages 0..STG-2.
    issue_group(0, 0);
    asm volatile("cp.async.commit_group;" ::: "memory");
    issue_group(1, 1);
    asm volatile("cp.async.commit_group;" ::: "memory");

#pragma unroll
    for (int i = 0; i < ITERS; i++) {
        // Issue group i+STG-1 (if any); always commit to keep group counting
        // uniform (empty commit groups complete immediately).
        if (i + STG - 1 < ITERS)
            issue_group(i + STG - 1, (i + STG - 1) % STG);
        asm volatile("cp.async.commit_group;" ::: "memory");
        // Allow the 2 newest groups to remain in flight; group i is done.
        asm volatile("cp.async.wait_group %0;" :: "n"(STG - 1) : "memory");
        __syncwarp();

        int s = i % STG;
        int idot[GRP];
#pragma unroll
        for (int j = 0; j < GRP; j++) {
            uint4 qa = *reinterpret_cast<const uint4*>(
                &sbuf[wslot][s][j * 512 + lane * 16]);
            uint4 qb = *reinterpret_cast<const uint4*>(
                &sbuf[wslot][s][(GRP + j) * 512 + lane * 16]);
            int t = __dp4a((int)qa.x, (int)qb.x, 0);
            t = __dp4a((int)qa.y, (int)qb.y, t);
            t = __dp4a((int)qa.z, (int)qb.z, t);
            t = __dp4a((int)qa.w, (int)qb.w, t);
            idot[j] = t;
        }
#pragma unroll
        for (int j = 0; j < GRP; j++)
            idot[j] = __reduce_add_sync(0xFFFFFFFFu, idot[j]);

        // Lanes 0..GRP-1 run the scalar epilogues in parallel.
        if (lane < GRP) {
            int e = ebase + i * GRP + lane;
            if (e < n_edges) {
                int mydot = (lane == 0) ? idot[0] : idot[GRP - 1];
                int mia = ia[i * GRP + lane];
                int mib = ib[i * GRP + lane];
                float2 ca = g_c[mia];
                float2 cb = g_c[mib];
                float dot_n = (float)mydot * ca.x * cb.x;
                float d2 = 2.0f - 2.0f * dot_n
                         + 2.0f * EPS * (ca.y - cb.y)
                         + (float)D * EPS * EPS;
                d2 = fmaxf(d2, 0.0f);
                float v = 1.0f - sqrtf(d2);
                out[e] = 1.0f / (1.0f + __expf(-v));
            }
        }
    }
}

// Fallback (fp32 fused, one warp per edge) if n_nodes exceeds static capacity.
__global__ void __launch_bounds__(256)
edge_decoder_f32_kernel(const float* __restrict__ z,
                        const void* __restrict__ edge_index,
                        float* __restrict__ out,
                        int n_edges)
{
    int e = (blockIdx.x * blockDim.x + threadIdx.x) >> 5;
    int lane = threadIdx.x & 31;
    if (e >= n_edges) return;

    long long ia, ib;
    if (g_idx_is64) {
        const long long* ei = (const long long*)edge_index;
        ia = ei[e];
        ib = ei[e + n_edges];
    } else {
        const int* ei = (const int*)edge_index;
        ia = ei[e];
        ib = ei[e + n_edges];
    }

    const float4* A = reinterpret_cast<const float4*>(z + ia * (long long)D);
    const float4* B = reinterpret_cast<const float4*>(z + ib * (long long)D);

    float dot = 0.f, na2 = 0.f, nb2 = 0.f, sa = 0.f, sb = 0.f;
    float4 av[4], bv[4];
#pragma unroll
    for (int j = 0; j < 4; j++) {
        av[j] = A[lane + 32 * j];
        bv[j] = B[lane + 32 * j];
    }
#pragma unroll
    for (int j = 0; j < 4; j++) {
        float4 a = av[j], b = bv[j];
        dot = fmaf(a.x, b.x, dot); dot = fmaf(a.y, b.y, dot);
        dot = fmaf(a.z, b.z, dot); dot = fmaf(a.w, b.w, dot);
        na2 = fmaf(a.x, a.x, na2); na2 = fmaf(a.y, a.y, na2);
        na2 = fmaf(a.z, a.z, na2); na2 = fmaf(a.w, a.w, na2);
        nb2 = fmaf(b.x, b.x, nb2); nb2 = fmaf(b.y, b.y, nb2);
        nb2 = fmaf(b.z, b.z, nb2); nb2 = fmaf(b.w, b.w, nb2);
        sa += a.x + a.y + a.z + a.w;
        sb += b.x + b.y + b.z + b.w;
    }
#pragma unroll
    for (int off = 16; off > 0; off >>= 1) {
        dot += __shfl_xor_sync(0xFFFFFFFFu, dot, off);
        na2 += __shfl_xor_sync(0xFFFFFFFFu, na2, off);
        nb2 += __shfl_xor_sync(0xFFFFFFFFu, nb2, off);
        sa  += __shfl_xor_sync(0xFFFFFFFFu, sa,  off);
        sb  += __shfl_xor_sync(0xFFFFFFFFu, sb,  off);
    }
    if (lane == 0) {
        float inva = rsqrtf(na2);
        float invb = rsqrtf(nb2);
        float d2 = 2.0f - 2.0f * dot * inva * invb
                 + 2.0f * EPS * (sa * inva - sb * invb)
                 + (float)D * EPS * EPS;
        d2 = fmaxf(d2, 0.0f);
        float v = 1.0f - sqrtf(d2);
        out[e] = 1.0f / (1.0f + __expf(-v));
    }
}

extern "C" void kernel_launch(void* const* d_in, const int* in_sizes, int n_in,
                              void* d_out, int out_size)
{
    const float* z = (const float*)d_in[0];
    const void* edge_index = d_in[1];
    float* out = (float*)d_out;

    int n_nodes = in_sizes[0] / D;
    int n_edges = in_sizes[1] / 2;

    if (n_nodes <= NODE_CAP) {
        int ngrid = (n_nodes + 7) / 8;                 // 8 warps/block
        prep_q8_kernel<<<ngrid, 256>>>((const float4*)z,
                                       (const int*)edge_index, n_nodes);
        int nwarps = (n_edges + EPW - 1) / EPW;        // 8 edges per warp
        int egrid = (nwarps + 3) / 4;                  // 4 warps/block
        edge_decoder_pipe_kernel<<<egrid, 128>>>(edge_index, out, n_edges);
    } else {
        detect_idx_dtype_kernel<<<1, 32>>>((const int*)edge_index);
        int egrid = (n_edges + 7) / 8;
        edge_decoder_f32_kernel<<<egrid, 256>>>(z, edge_index, out, n_edges);
    }
}

// round 10
// speedup vs baseline: 1.0241x; 1.0241x over previous
#include <cuda_runtime.h>
#include <stdint.h>

#define D 512               // embedding dim (fixed by problem)
#define EPS 1e-6f
#define NODE_CAP 50000      // capacity of the static int8 copy

#define GRP 3               // edges per commit group
#define NGRP 2              // groups per warp
#define EPW (GRP * NGRP)    // edges per warp = 6
#define WPB 4               // warps per block
// smem per warp: NGRP * GRP * 2 rows * 512 B = 6 KB; per block 24 KB

// Runtime index-dtype flag: 1 if edge_index is int64, 0 if int32.
__device__ int g_idx_is64;

// int8 copy of z: one row = 512 bytes. 25.6 MB (mostly L2-resident).
__device__ __align__(16) unsigned char g_q8[(size_t)NODE_CAP * 512];
// combined per-node constants: c.x = (absmax/127)*inv_norm, c.y = sum*inv_norm
__device__ float2 g_c[NODE_CAP];

// Standalone detect (only used on the fp32 fallback path)
__global__ void detect_idx_dtype_kernel(const int* __restrict__ raw)
{
    int lane = threadIdx.x & 31;
    int lo = raw[2 * lane];
    int hi = raw[2 * lane + 1];
    unsigned bad = __ballot_sync(0xFFFFFFFFu, hi != 0 || lo < 0);
    if (lane == 0) g_idx_is64 = (bad == 0) ? 1 : 0;
}

__device__ __forceinline__ unsigned pack4_q(float4 v, float k)
{
    int q0 = __float2int_rn(v.x * k);
    int q1 = __float2int_rn(v.y * k);
    int q2 = __float2int_rn(v.z * k);
    int q3 = __float2int_rn(v.w * k);
    return (q0 & 0xFF) | ((q1 & 0xFF) << 8) | ((q2 & 0xFF) << 16)
         | ((q3 & 0xFF) << 24);
}

// Pass 1: one warp per node. Stream z row with __ldcs (evict-first),
// compute exact fp32 norm/sum and absmax, quantize to int8.
// Warp 0 additionally performs index-dtype detection.
__global__ void __launch_bounds__(256)
prep_q8_kernel(const float4* __restrict__ z4,
               const int* __restrict__ raw_edges,
               int n_nodes)
{
    int warp = (blockIdx.x * blockDim.x + threadIdx.x) >> 5;
    int lane = threadIdx.x & 31;

    if (warp == 0) {
        // int64 little-endian indices in [0, n_nodes) => hi word always 0.
        int lo = raw_edges[2 * lane];
        int hi = raw_edges[2 * lane + 1];
        unsigned bad = __ballot_sync(0xFFFFFFFFu, hi != 0 || lo < 0);
        if (lane == 0) g_idx_is64 = (bad == 0) ? 1 : 0;
    }
    if (warp >= n_nodes) return;

    const float4* __restrict__ R = z4 + (size_t)warp * (D / 4);
    float4 v[4];
#pragma unroll
    for (int j = 0; j < 4; j++) v[j] = __ldcs(&R[lane + 32 * j]);

    float na2 = 0.f, sa = 0.f, mx = 0.f;
#pragma unroll
    for (int j = 0; j < 4; j++) {
        float4 a = v[j];
        na2 = fmaf(a.x, a.x, na2); na2 = fmaf(a.y, a.y, na2);
        na2 = fmaf(a.z, a.z, na2); na2 = fmaf(a.w, a.w, na2);
        sa += a.x + a.y + a.z + a.w;
        mx = fmaxf(mx, fmaxf(fmaxf(fabsf(a.x), fabsf(a.y)),
                             fmaxf(fabsf(a.z), fabsf(a.w))));
    }

#pragma unroll
    for (int off = 16; off > 0; off >>= 1) {
        na2 += __shfl_xor_sync(0xFFFFFFFFu, na2, off);
        sa  += __shfl_xor_sync(0xFFFFFFFFu, sa,  off);
        mx  = fmaxf(mx, __shfl_xor_sync(0xFFFFFFFFu, mx, off));
    }

    mx = fmaxf(mx, 1e-20f);
    float k = 127.0f / mx;

    uint4 q;
    q.x = pack4_q(v[0], k);
    q.y = pack4_q(v[1], k);
    q.z = pack4_q(v[2], k);
    q.w = pack4_q(v[3], k);
    reinterpret_cast<uint4*>(g_q8)[(size_t)warp * 32 + lane] = q;

    if (lane == 0) {
        float inv = rsqrtf(na2);
        float2 c;
        c.x = mx * (1.0f / 127.0f) * inv;   // dequant * inv_norm (for dot)
        c.y = sa * inv;                     // sum * inv_norm     (for eps term)
        g_c[warp] = c;
    }
}

// Pass 2: cp.async edge decoder, 6 edges/warp in TWO commit groups of 3.
// Both groups' 12 rows are issued back-to-back (full burst MLP), but the
// wait is split: compute on group 0 overlaps the in-flight loads of group 1.
// 6 KB smem per warp -> 24 KB/block -> ~9 blocks/SM (~36 warps) vs 6 before.
__global__ void __launch_bounds__(WPB * 32)
edge_decoder_q8g2_kernel(const void* __restrict__ edge_index,
                         float* __restrict__ out,
                         int n_edges)
{
    __shared__ __align__(16) unsigned char sbuf[WPB][NGRP][GRP * 2 * 512];

    int wslot = threadIdx.x >> 5;
    int lane  = threadIdx.x & 31;
    int warp  = blockIdx.x * WPB + wslot;
    int ebase = warp * EPW;
    if (ebase >= n_edges) return;

    // Prefetch all 12 node indices (int32; node ids < 50K). Broadcast loads.
    int ia[EPW], ib[EPW];
    if (g_idx_is64) {
        const long long* ei = (const long long*)edge_index;
#pragma unroll
        for (int j = 0; j < EPW; j++) {
            int e = min(ebase + j, n_edges - 1);
            ia[j] = (int)ei[e];
            ib[j] = (int)ei[e + n_edges];
        }
    } else {
        const int* ei = (const int*)edge_index;
#pragma unroll
        for (int j = 0; j < EPW; j++) {
            int e = min(ebase + j, n_edges - 1);
            ia[j] = ei[e];
            ib[j] = ei[e + n_edges];
        }
    }

    unsigned sbase;
    {
        void* p = &sbuf[wslot][0][0];
        asm("{ .reg .u64 t; cvta.to.shared.u64 t, %1; cvt.u32.u64 %0, t; }"
            : "=r"(sbase) : "l"(p));
    }

    // Issue both groups back-to-back: 12 independent 16B cp.asyncs per lane.
#pragma unroll
    for (int g = 0; g < NGRP; g++) {
        unsigned sb = sbase + g * (GRP * 2 * 512) + lane * 16;
#pragma unroll
        for (int j = 0; j < GRP; j++) {
            const unsigned char* srcA =
                g_q8 + (size_t)ia[g * GRP + j] * 512 + lane * 16;
            const unsigned char* srcB =
                g_q8 + (size_t)ib[g * GRP + j] * 512 + lane * 16;
            asm volatile("cp.async.cg.shared.global [%0], [%1], 16;"
                         :: "r"(sb + j * 512), "l"(srcA) : "memory");
            asm volatile("cp.async.cg.shared.global [%0], [%1], 16;"
                         :: "r"(sb + (GRP + j) * 512), "l"(srcB) : "memory");
        }
        asm volatile("cp.async.commit_group;" ::: "memory");
    }

    // Process group 0 while group 1 is still in flight, then group 1.
#pragma unroll
    for (int g = 0; g < NGRP; g++) {
        if (g == 0)
            asm volatile("cp.async.wait_group 1;" ::: "memory");
        else
            asm volatile("cp.async.wait_group 0;" ::: "memory");

        int idot[GRP];
#pragma unroll
        for (int j = 0; j < GRP; j++) {
            uint4 qa = *reinterpret_cast<const uint4*>(
                &sbuf[wslot][g][j * 512 + lane * 16]);
            uint4 qb = *reinterpret_cast<const uint4*>(
                &sbuf[wslot][g][(GRP + j) * 512 + lane * 16]);
            int t = __dp4a((int)qa.x, (int)qb.x, 0);
            t = __dp4a((int)qa.y, (int)qb.y, t);
            t = __dp4a((int)qa.z, (int)qb.z, t);
            t = __dp4a((int)qa.w, (int)qb.w, t);
            idot[j] = t;
        }
#pragma unroll
        for (int j = 0; j < GRP; j++)
            idot[j] = __reduce_add_sync(0xFFFFFFFFu, idot[j]);

        // Lanes 0..GRP-1 run the scalar epilogues in parallel.
        if (lane < GRP) {
            int e = ebase + g * GRP + lane;
            if (e < n_edges) {
                int mydot = idot[0];
#pragma unroll
                for (int j = 1; j < GRP; j++) if (lane == j) mydot = idot[j];
                int mia = ia[g * GRP + lane];
                int mib = ib[g * GRP + lane];
                float2 ca = g_c[mia];
                float2 cb = g_c[mib];
                float dot_n = (float)mydot * ca.x * cb.x;
                float d2 = 2.0f - 2.0f * dot_n
                         + 2.0f * EPS * (ca.y - cb.y)
                         + (float)D * EPS * EPS;
                d2 = fmaxf(d2, 0.0f);
                float v = 1.0f - sqrtf(d2);
                out[e] = 1.0f / (1.0f + __expf(-v));
            }
        }
    }
}

// Fallback (fp32 fused, one warp per edge) if n_nodes exceeds static capacity.
__global__ void __launch_bounds__(256)
edge_decoder_f32_kernel(const float* __restrict__ z,
                        const void* __restrict__ edge_index,
                        float* __restrict__ out,
                        int n_edges)
{
    int e = (blockIdx.x * blockDim.x + threadIdx.x) >> 5;
    int lane = threadIdx.x & 31;
    if (e >= n_edges) return;

    long long ia, ib;
    if (g_idx_is64) {
        const long long* ei = (const long long*)edge_index;
        ia = ei[e];
        ib = ei[e + n_edges];
    } else {
        const int* ei = (const int*)edge_index;
        ia = ei[e];
        ib = ei[e + n_edges];
    }

    const float4* A = reinterpret_cast<const float4*>(z + ia * (long long)D);
    const float4* B = reinterpret_cast<const float4*>(z + ib * (long long)D);

    float dot = 0.f, na2 = 0.f, nb2 = 0.f, sa = 0.f, sb = 0.f;
    float4 av[4], bv[4];
#pragma unroll
    for (int j = 0; j < 4; j++) {
        av[j] = A[lane + 32 * j];
        bv[j] = B[lane + 32 * j];
    }
#pragma unroll
    for (int j = 0; j < 4; j++) {
        float4 a = av[j], b = bv[j];
        dot = fmaf(a.x, b.x, dot); dot = fmaf(a.y, b.y, dot);
        dot = fmaf(a.z, b.z, dot); dot = fmaf(a.w, b.w, dot);
        na2 = fmaf(a.x, a.x, na2); na2 = fmaf(a.y, a.y, na2);
        na2 = fmaf(a.z, a.z, na2); na2 = fmaf(a.w, a.w, na2);
        nb2 = fmaf(b.x, b.x, nb2); nb2 = fmaf(b.y, b.y, nb2);
        nb2 = fmaf(b.z, b.z, nb2); nb2 = fmaf(b.w, b.w, nb2);
        sa += a.x + a.y + a.z + a.w;
        sb += b.x + b.y + b.z + b.w;
    }
#pragma unroll
    for (int off = 16; off > 0; off >>= 1) {
        dot += __shfl_xor_sync(0xFFFFFFFFu, dot, off);
        na2 += __shfl_xor_sync(0xFFFFFFFFu, na2, off);
        nb2 += __shfl_xor_sync(0xFFFFFFFFu, nb2, off);
        sa  += __shfl_xor_sync(0xFFFFFFFFu, sa,  off);
        sb  += __shfl_xor_sync(0xFFFFFFFFu, sb,  off);
    }
    if (lane == 0) {
        float inva = rsqrtf(na2);
        float invb = rsqrtf(nb2);
        float d2 = 2.0f - 2.0f * dot * inva * invb
                 + 2.0f * EPS * (sa * inva - sb * invb)
                 + (float)D * EPS * EPS;
        d2 = fmaxf(d2, 0.0f);
        float v = 1.0f - sqrtf(d2);
        out[e] = 1.0f / (1.0f + __expf(-v));
    }
}

extern "C" void kernel_launch(void* const* d_in, const int* in_sizes, int n_in,
                              void* d_out, int out_size)
{
    const float* z = (const float*)d_in[0];
    const void* edge_index = d_in[1];
    float* out = (float*)d_out;

    int n_nodes = in_sizes[0] / D;
    int n_edges = in_sizes[1] / 2;

    if (n_nodes <= NODE_CAP) {
        int ngrid = (n_nodes + 7) / 8;                 // 8 warps/block
        prep_q8_kernel<<<ngrid, 256>>>((const float4*)z,
                                       (const int*)edge_index, n_nodes);
        int nwarps = (n_edges + EPW - 1) / EPW;        // 6 edges per warp
        int egrid = (nwarps + WPB - 1) / WPB;
        edge_decoder_q8g2_kernel<<<egrid, WPB * 32>>>(edge_index, out, n_edges);
    } else {
        detect_idx_dtype_kernel<<<1, 32>>>((const int*)edge_index);
        int egrid = (n_edges + 7) / 8;
        edge_decoder_f32_kernel<<<egrid, 256>>>(z, edge_index, out, n_edges);
    }
}

// round 12
// speedup vs baseline: 1.1746x; 1.1469x over previous
#include <cuda_runtime.h>
#include <stdint.h>

#define D 512               // embedding dim (fixed by problem)
#define EPS 1e-6f
#define NODE_CAP 50000      // capacity of the static int8 copy

#define EPW 8               // edges per warp
#define WPB 2               // warps per block (16 KB smem -> ~14 blocks/SM)

// Runtime index-dtype flag: 1 if edge_index is int64, 0 if int32.
__device__ int g_idx_is64;

// int8 copy of z: one row = 512 bytes. 25.6 MB; written with evict_last
// cache policy so it stays L2-resident across the z stream and edge pass.
__device__ __align__(16) unsigned char g_q8[(size_t)NODE_CAP * 512];
// combined per-node constants: c.x = (absmax/127)*inv_norm, c.y = sum*inv_norm
__device__ float2 g_c[NODE_CAP];

// Standalone detect (only used on the fp32 fallback path)
__global__ void detect_idx_dtype_kernel(const int* __restrict__ raw)
{
    int lane = threadIdx.x & 31;
    int lo = raw[2 * lane];
    int hi = raw[2 * lane + 1];
    unsigned bad = __ballot_sync(0xFFFFFFFFu, hi != 0 || lo < 0);
    if (lane == 0) g_idx_is64 = (bad == 0) ? 1 : 0;
}

__device__ __forceinline__ unsigned pack4_q(float4 v, float k)
{
    int q0 = __float2int_rn(v.x * k);
    int q1 = __float2int_rn(v.y * k);
    int q2 = __float2int_rn(v.z * k);
    int q3 = __float2int_rn(v.w * k);
    return (q0 & 0xFF) | ((q1 & 0xFF) << 8) | ((q2 & 0xFF) << 16)
         | ((q3 & 0xFF) << 24);
}

// Pass 1: one warp per node. z row read with __ldcs (evict-first), q8 table
// written with createpolicy(evict_last) + st.global.L2::cache_hint so the
// edge pass finds it in L2 instead of re-fetching 25.6 MB from DRAM.
__global__ void __launch_bounds__(256)
prep_q8_kernel(const float4* __restrict__ z4,
               const int* __restrict__ raw_edges,
               int n_nodes)
{
    int warp = (blockIdx.x * blockDim.x + threadIdx.x) >> 5;
    int lane = threadIdx.x & 31;

    if (warp == 0) {
        // int64 little-endian indices in [0, n_nodes) => hi word always 0.
        int lo = raw_edges[2 * lane];
        int hi = raw_edges[2 * lane + 1];
        unsigned bad = __ballot_sync(0xFFFFFFFFu, hi != 0 || lo < 0);
        if (lane == 0) g_idx_is64 = (bad == 0) ? 1 : 0;
    }
    if (warp >= n_nodes) return;

    const float4* __restrict__ R = z4 + (size_t)warp * (D / 4);
    float4 v[4];
#pragma unroll
    for (int j = 0; j < 4; j++) v[j] = __ldcs(&R[lane + 32 * j]);

    float na2 = 0.f, sa = 0.f, mx = 0.f;
#pragma unroll
    for (int j = 0; j < 4; j++) {
        float4 a = v[j];
        na2 = fmaf(a.x, a.x, na2); na2 = fmaf(a.y, a.y, na2);
        na2 = fmaf(a.z, a.z, na2); na2 = fmaf(a.w, a.w, na2);
        sa += a.x + a.y + a.z + a.w;
        mx = fmaxf(mx, fmaxf(fmaxf(fabsf(a.x), fabsf(a.y)),
                             fmaxf(fabsf(a.z), fabsf(a.w))));
    }

#pragma unroll
    for (int off = 16; off > 0; off >>= 1) {
        na2 += __shfl_xor_sync(0xFFFFFFFFu, na2, off);
        sa  += __shfl_xor_sync(0xFFFFFFFFu, sa,  off);
        mx  = fmaxf(mx, __shfl_xor_sync(0xFFFFFFFFu, mx, off));
    }

    mx = fmaxf(mx, 1e-20f);
    float k = 127.0f / mx;

    unsigned q0 = pack4_q(v[0], k);
    unsigned q1 = pack4_q(v[1], k);
    unsigned q2 = pack4_q(v[2], k);
    unsigned q3 = pack4_q(v[3], k);

    unsigned long long pol;
    asm("createpolicy.fractional.L2::evict_last.b64 %0, 1.0;" : "=l"(pol));

    {
        uint4* dst = reinterpret_cast<uint4*>(g_q8) + (size_t)warp * 32 + lane;
        asm volatile(
            "st.global.L2::cache_hint.v4.u32 [%0], {%1,%2,%3,%4}, %5;"
            :: "l"(dst), "r"(q0), "r"(q1), "r"(q2), "r"(q3), "l"(pol)
            : "memory");
    }

    if (lane == 0) {
        float inv = rsqrtf(na2);
        float cx = mx * (1.0f / 127.0f) * inv;  // dequant * inv_norm
        float cy = sa * inv;                    // sum * inv_norm
        float2* dst = &g_c[warp];
        asm volatile(
            "st.global.L2::cache_hint.v2.f32 [%0], {%1,%2}, %3;"
            :: "l"(dst), "f"(cx), "f"(cy), "l"(pol)
            : "memory");
    }
}

// Pass 2: cp.async edge decoder, 8 edges/warp, 16 rows issued as two commit
// groups of 8 (split waits give partial load/compute overlap). 2 warps/block
// keeps smem at 16 KB -> ~14 blocks/SM, ~28 warps resident.
__global__ void __launch_bounds__(WPB * 32)
edge_decoder_q8b_kernel(const void* __restrict__ edge_index,
                        float* __restrict__ out,
                        int n_edges)
{
    __shared__ __align__(16) unsigned char sbuf[WPB][16 * 512];

    int wslot = threadIdx.x >> 5;
    int lane  = threadIdx.x & 31;
    int warp  = blockIdx.x * WPB + wslot;
    int e0 = warp * EPW;
    if (e0 >= n_edges) return;

    // Prefetch 16 node indices (int32; node ids < 50K). Broadcast loads.
    int idx[16];             // [0..7] = a-side, [8..15] = b-side
    if (g_idx_is64) {
        const long long* ei = (const long long*)edge_index;
#pragma unroll
        for (int j = 0; j < 8; j++) {
            int e = min(e0 + j, n_edges - 1);
            idx[j]     = (int)ei[e];
            idx[8 + j] = (int)ei[e + n_edges];
        }
    } else {
        const int* ei = (const int*)edge_index;
#pragma unroll
        for (int j = 0; j < 8; j++) {
            int e = min(e0 + j, n_edges - 1);
            idx[j]     = ei[e];
            idx[8 + j] = ei[e + n_edges];
        }
    }

    unsigned sbase;
    {
        void* p = &sbuf[wslot][0];
        asm("{ .reg .u64 t; cvta.to.shared.u64 t, %1; cvt.u32.u64 %0, t; }"
            : "=r"(sbase) : "l"(p));
    }

    // Burst-issue all 16 rows as two commit groups of 8 rows
    // (rows for edges 0-3 first, then edges 4-7).
#pragma unroll
    for (int h = 0; h < 2; h++) {
#pragma unroll
        for (int j = 0; j < 4; j++) {
            int ea = h * 4 + j;                 // edge slot within warp
            unsigned dA = sbase + ea * 512 + lane * 16;
            unsigned dB = sbase + (8 + ea) * 512 + lane * 16;
            const unsigned char* sA = g_q8 + (size_t)idx[ea] * 512 + lane * 16;
            const unsigned char* sB = g_q8 + (size_t)idx[8 + ea] * 512 + lane * 16;
            asm volatile("cp.async.cg.shared.global [%0], [%1], 16;"
                         :: "r"(dA), "l"(sA) : "memory");
            asm volatile("cp.async.cg.shared.global [%0], [%1], 16;"
                         :: "r"(dB), "l"(sB) : "memory");
        }
        asm volatile("cp.async.commit_group;" ::: "memory");
    }

    int idot[8];
#pragma unroll
    for (int h = 0; h < 2; h++) {
        if (h == 0)
            asm volatile("cp.async.wait_group 1;" ::: "memory");
        else
            asm volatile("cp.async.wait_group 0;" ::: "memory");

#pragma unroll
        for (int j = 0; j < 4; j++) {
            int ea = h * 4 + j;
            uint4 qa = *reinterpret_cast<const uint4*>(
                &sbuf[wslot][ea * 512 + lane * 16]);
            uint4 qb = *reinterpret_cast<const uint4*>(
                &sbuf[wslot][(8 + ea) * 512 + lane * 16]);
            int t = __dp4a((int)qa.x, (int)qb.x, 0);
            t = __dp4a((int)qa.y, (int)qb.y, t);
            t = __dp4a((int)qa.z, (int)qb.z, t);
            t = __dp4a((int)qa.w, (int)qb.w, t);
            idot[ea] = t;
        }
#pragma unroll
        for (int j = 0; j < 4; j++)
            idot[h * 4 + j] = __reduce_add_sync(0xFFFFFFFFu, idot[h * 4 + j]);
    }

    // Lanes 0-7 handle one edge each, in parallel.
    if (lane < 8 && e0 + lane < n_edges) {
        int mydot = idot[0];
        int mia = idx[0], mib = idx[8];
#pragma unroll
        for (int j = 1; j < 8; j++) {
            if (lane == j) { mydot = idot[j]; mia = idx[j]; mib = idx[8 + j]; }
        }

        float2 ca = g_c[mia];
        float2 cb = g_c[mib];
        float dot_n = (float)mydot * ca.x * cb.x;
        float d2 = 2.0f - 2.0f * dot_n
                 + 2.0f * EPS * (ca.y - cb.y)
                 + (float)D * EPS * EPS;
        d2 = fmaxf(d2, 0.0f);
        float v = 1.0f - sqrtf(d2);
        out[e0 + lane] = 1.0f / (1.0f + __expf(-v));
    }
}

// Fallback (fp32 fused, one warp per edge) if n_nodes exceeds static capacity.
__global__ void __launch_bounds__(256)
edge_decoder_f32_kernel(const float* __restrict__ z,
                        const void* __restrict__ edge_index,
                        float* __restrict__ out,
                        int n_edges)
{
    int e = (blockIdx.x * blockDim.x + threadIdx.x) >> 5;
    int lane = threadIdx.x & 31;
    if (e >= n_edges) return;

    long long ia, ib;
    if (g_idx_is64) {
        const long long* ei = (const long long*)edge_index;
        ia = ei[e];
        ib = ei[e + n_edges];
    } else {
        const int* ei = (const int*)edge_index;
        ia = ei[e];
        ib = ei[e + n_edges];
    }

    const float4* A = reinterpret_cast<const float4*>(z + ia * (long long)D);
    const float4* B = reinterpret_cast<const float4*>(z + ib * (long long)D);

    float dot = 0.f, na2 = 0.f, nb2 = 0.f, sa = 0.f, sb = 0.f;
    float4 av[4], bv[4];
#pragma unroll
    for (int j = 0; j < 4; j++) {
        av[j] = A[lane + 32 * j];
        bv[j] = B[lane + 32 * j];
    }
#pragma unroll
    for (int j = 0; j < 4; j++) {
        float4 a = av[j], b = bv[j];
        dot = fmaf(a.x, b.x, dot); dot = fmaf(a.y, b.y, dot);
        dot = fmaf(a.z, b.z, dot); dot = fmaf(a.w, b.w, dot);
        na2 = fmaf(a.x, a.x, na2); na2 = fmaf(a.y, a.y, na2);
        na2 = fmaf(a.z, a.z, na2); na2 = fmaf(a.w, a.w, na2);
        nb2 = fmaf(b.x, b.x, nb2); nb2 = fmaf(b.y, b.y, nb2);
        nb2 = fmaf(b.z, b.z, nb2); nb2 = fmaf(b.w, b.w, nb2);
        sa += a.x + a.y + a.z + a.w;
        sb += b.x + b.y + b.z + b.w;
    }
#pragma unroll
    for (int off = 16; off > 0; off >>= 1) {
        dot += __shfl_xor_sync(0xFFFFFFFFu, dot, off);
        na2 += __shfl_xor_sync(0xFFFFFFFFu, na2, off);
        nb2 += __shfl_xor_sync(0xFFFFFFFFu, nb2, off);
        sa  += __shfl_xor_sync(0xFFFFFFFFu, sa,  off);
        sb  += __shfl_xor_sync(0xFFFFFFFFu, sb,  off);
    }
    if (lane == 0) {
        float inva = rsqrtf(na2);
        float invb = rsqrtf(nb2);
        float d2 = 2.0f - 2.0f * dot * inva * invb
                 + 2.0f * EPS * (sa * inva - sb * invb)
                 + (float)D * EPS * EPS;
        d2 = fmaxf(d2, 0.0f);
        float v = 1.0f - sqrtf(d2);
        out[e] = 1.0f / (1.0f + __expf(-v));
    }
}

extern "C" void kernel_launch(void* const* d_in, const int* in_sizes, int n_in,
                              void* d_out, int out_size)
{
    const float* z = (const float*)d_in[0];
    const void* edge_index = d_in[1];
    float* out = (float*)d_out;

    int n_nodes = in_sizes[0] / D;
    int n_edges = in_sizes[1] / 2;

    if (n_nodes <= NODE_CAP) {
        int ngrid = (n_nodes + 7) / 8;                 // 8 warps/block
        prep_q8_kernel<<<ngrid, 256>>>((const float4*)z,
                                       (const int*)edge_index, n_nodes);
        int nwarps = (n_edges + EPW - 1) / EPW;        // 8 edges per warp
        int egrid = (nwarps + WPB - 1) / WPB;
        edge_decoder_q8b_kernel<<<egrid, WPB * 32>>>(edge_index, out, n_edges);
    } else {
        detect_idx_dtype_kernel<<<1, 32>>>((const int*)edge_index);
        int egrid = (n_edges + 7) / 8;
        edge_decoder_f32_kernel<<<egrid, 256>>>(z, edge_index, out, n_edges);
    }
}